// round 4
// baseline (speedup 1.0000x reference)
#include <cuda_runtime.h>

// B=16, C=64, H=W=256, STRIDE=2, IN_KS=OUT_KS=3
#define HH 256
#define WW 256
#define HP 128
#define WP 128
#define TH 32              // output rows per block
#define NT 8               // tiles per plane
#define CAN_H 34           // image rows R0-1 .. R0+32
#define CAN_W 260          // 258 used, padded for float4
#define PR_H 19            // prov rows I0-1 .. I0+17
#define PR_W 136           // ushort; cell j at index j+4, halos at 3 and 132

__global__ __launch_bounds__(256, 5)
void morph_unpool_dilate_kernel(const float* __restrict__ f,
                                const int*   __restrict__ prov,
                                float*       __restrict__ out)
{
    __shared__ float          canvas[CAN_H][CAN_W];
    __shared__ unsigned short sprov[PR_H][PR_W];

    const int   bid  = blockIdx.x;
    const int   bc   = bid >> 3;
    const int   tile = bid & 7;
    const int   R0   = tile * TH;
    const int   I0   = tile * (TH / 2);
    const int   tid  = threadIdx.x;
    const int   lane = tid & 31;
    const int   warp = tid >> 5;
    const float NEG  = __int_as_float(0xff800000);

    const float* fb  = f + (size_t)bc * (HP * WP);
    const int4*  pb4 = (const int4*)(prov + (size_t)bc * (HP * WP));

    // ---- Phase 1a: unconditional float4 zero-fill of canvas ----
    {
        float4  z  = make_float4(0.f, 0.f, 0.f, 0.f);
        float4* c4 = (float4*)&canvas[0][0];
        #pragma unroll
        for (int i = tid; i < CAN_H * 65; i += 256) c4[i] = z;
    }

    // ---- Phase 1b: stage provenance as u16 ----
    for (int idx = tid; idx < PR_H * 32; idx += 256) {
        int li = idx >> 5;                 // cell row i = I0-1+li
        int g  = idx & 31;
        int i  = I0 - 1 + li;
        ushort4 s = make_ushort4(0, 0, 0, 0);   // bottom/top sentinel
        if ((unsigned)i < HP) {
            int4 p = pb4[i * 32 + g];
            s = make_ushort4((unsigned short)p.x, (unsigned short)p.y,
                             (unsigned short)p.z, (unsigned short)p.w);
        }
        *(ushort4*)&sprov[li][(g << 2) + 4] = s;
    }
    if (tid < PR_H * 2) {                  // column halos
        int li = tid >> 1;
        if (tid & 1) sprov[li][132] = 0;       // j=128 (comparers have t>=254)
        else         sprov[li][3]   = 0xFFFF;  // j=-1  (comparers have c<=2)
    }
    __syncthreads();

    // ---- Phase 2a: -inf borders (addresses never targeted by the scatter) ----
    if (tid < CAN_H * 2) {
        int r = tid >> 1;
        canvas[r][(tid & 1) ? (WW + 1) : 0] = NEG;
    }
    if (tile == 0 && tid < 65)
        ((float4*)&canvas[0][0])[tid] = make_float4(NEG, NEG, NEG, NEG);
    if (tile == NT - 1 && tid < 65)
        ((float4*)&canvas[CAN_H - 1][0])[tid] = make_float4(NEG, NEG, NEG, NEG);

    // ---- Phase 2b: race-free last-write-wins scatter, stride-1 lanes ----
    // Cell (i,j) writes iff none of (i,j+1),(i+1,j-1),(i+1,j),(i+1,j+1)
    // (all higher linear index) targets the same pixel.
    for (int task = warp; task < 18 * 4; task += 8) {
        const int li = task >> 2;          // 0..17
        const int j  = ((task & 3) << 5) + lane;
        const int i  = I0 - 1 + li;
        if ((unsigned)i < HP) {            // uniform across warp
            int t = sprov[li][j + 4];
            int b = sprov[li + 1][j + 4];
            int n1 = __shfl_down_sync(0xffffffffu, t, 1);   // (i,   j+1)
            int n2 = __shfl_up_sync  (0xffffffffu, b, 1);   // (i+1, j-1)
            int n4 = __shfl_down_sync(0xffffffffu, b, 1);   // (i+1, j+1)
            if (lane == 31) {
                n1 = sprov[li][j + 5];
                n4 = sprov[li + 1][j + 5];
            }
            if (lane == 0)
                n2 = sprov[li + 1][j + 3];
            float fv = fb[i * WP + j];     // coalesced
            bool sup = (n1 == t) | (n2 == t) | (b == t) | (n4 == t);
            int  lr  = (t >> 8) - R0 + 1;
            if (!sup && (unsigned)lr < CAN_H)
                canvas[lr][(t & 255) + 1] = fv;   // c ~ 2*lane -> 2-way max
        }
    }
    __syncthreads();

    // ---- Phase 3: separable 3x3 max, 8-row strips, rolling vertical max ----
    const int cb   = (tid & 63) << 2;
    const int base = (tid >> 6) << 3;
    float* ob = out + (size_t)bc * (HH * WW) + (size_t)(R0 + base) * WW + cb;

    auto hrow = [&](int cr) -> float4 {
        float4 a = *(const float4*)&canvas[cr][cb];
        float2 b = *(const float2*)&canvas[cr][cb + 4];
        float  m = fmaxf(a.y, a.z);
        float  n = fmaxf(a.w, b.x);
        float4 h;
        h.x = fmaxf(m, a.x);
        h.y = fmaxf(m, a.w);
        h.z = fmaxf(a.z, n);
        h.w = fmaxf(n, b.y);
        return h;
    };

    float4 h0 = hrow(base);
    float4 h1 = hrow(base + 1);
    #pragma unroll
    for (int k = 0; k < 8; k++) {
        float4 h2 = hrow(base + k + 2);
        float4 o;
        o.x = fmaxf(fmaxf(h0.x, h1.x), h2.x);
        o.y = fmaxf(fmaxf(h0.y, h1.y), h2.y);
        o.z = fmaxf(fmaxf(h0.z, h1.z), h2.z);
        o.w = fmaxf(fmaxf(h0.w, h1.w), h2.w);
        *(float4*)&ob[k * WW] = o;
        h0 = h1; h1 = h2;
    }
}

extern "C" void kernel_launch(void* const* d_in, const int* in_sizes, int n_in,
                              void* d_out, int out_size)
{
    const float* f    = (const float*)d_in[0];
    const int*   prov = (const int*)  d_in[1];
    float* out = (float*)d_out;
    morph_unpool_dilate_kernel<<<1024 * NT, 256>>>(f, prov, out);
}